// round 10
// baseline (speedup 1.0000x reference)
#include <cuda_runtime.h>

#define DD 4096
#define SMSZ 4224   // 4096 + 4096/32 pad floats

__device__ float g_dev[DD];

__global__ void compute_g_kernel(const float* __restrict__ eps,
                                 const float* __restrict__ g_mu,
                                 const float* __restrict__ g_rho) {
    int i = blockIdx.x * blockDim.x + threadIdx.x;
    if (i < DD) {
        float r = g_rho[i];
        g_dev[i] = g_mu[i] + log1pf(expf(r)) * eps[i];
    }
}

// Butterfly via FFMA with immediate multiplier +/-(1+2^-23) = 0x3F800001.
// The off-by-1ulp multiplier is NOT foldable to FADD, so ptxas must emit the
// FFMA src1-immediate form, which issues on the fma pipe at rt_SMSP=1
// (vs alu-pipe FADD at rt_SMSP=2). Error: b*(1+1.19e-7) per butterfly,
// <= ~3e-6 relative over 24 stages — far inside the 1e-3 gate.
__device__ __forceinline__ float ADD1(float a, float b) {
    float d; asm("fma.rn.f32 %0, %1, 0F3F800001, %2;" : "=f"(d) : "f"(b), "f"(a)); return d;
}
__device__ __forceinline__ float SUB1(float a, float b) {
    float d; asm("fma.rn.f32 %0, %1, 0FBF800001, %2;" : "=f"(d) : "f"(b), "f"(a)); return d;
}

// Scalar radix-16 FWHT over the register index (4 butterfly stages).
__device__ __forceinline__ void fwht16(float v[16]) {
#pragma unroll
    for (int s = 0; s < 4; s++) {
        const int h = 1 << s;
#pragma unroll
        for (int q = 0; q < 16; q += 2*h) {
#pragma unroll
            for (int j = 0; j < h; j++) {
                float a = v[q+j], b = v[q+j+h];
                v[q+j]   = ADD1(a, b);
                v[q+j+h] = SUB1(a, b);
            }
        }
    }
}

// y_row = s1 * FWHT( g * FWHT( s2 * x_row ) ),  FWHT_4096 = F_A . F_B . F_C
// (identical structure/layouts to the 41.5us trunk):
//   Phase A: regs = bits {0..3},  lanes = bits {4..8},  warps = bits {9..11}
//   Phase B: regs = bits {4..7},  lanes = bits {0,1,2,8,9}, warps = {3,10,11}
//   Phase C: regs = bits {8..11}, lanes = bits {0..4},  warps = bits {5..7}
// Additive carry-free pad swizzle phys(i) = i + (i>>5): bank-injective per
// warp for all three layouts; every LDS/STS address is base + immediate.
__global__ void __launch_bounds__(256, 5)
whvi_kernel(const float* __restrict__ x,
            const float* __restrict__ s1,
            const float* __restrict__ s2,
            float* __restrict__ out) {
    __shared__ float sm[SMSZ];

    const int t = threadIdx.x;
    const int l = t & 31;
    const int w = t >> 5;

    const int baseA = 16*l + 512*w;
    const int baseB = (l & 7) + 8*(w & 1) + 256*(l >> 3) + 1024*(w >> 1);
    const int baseC = l + 32*w;
    const int pA = baseA + (baseA >> 5);
    const int pB = baseB + (baseB >> 5);
    const int pC = baseC + (baseC >> 5);

    const long long row = blockIdx.x;
    const float* xr = x + row * DD;

    float v[16];

    // ---- P1: coalesced load, *s2, F_A ----
#pragma unroll
    for (int q = 0; q < 4; q++) {
        float4 a = *reinterpret_cast<const float4*>(xr + baseA + 4*q);
        float4 s = *reinterpret_cast<const float4*>(s2 + baseA + 4*q);
        v[4*q+0] = a.x * s.x;
        v[4*q+1] = a.y * s.y;
        v[4*q+2] = a.z * s.z;
        v[4*q+3] = a.w * s.w;
    }
    fwht16(v);
#pragma unroll
    for (int r = 0; r < 16; r++) sm[pA + r] = v[r];
    __syncthreads();

    // ---- P2: F_B ----  elem offset 16r -> phys offset 16r + (r>>1)
#pragma unroll
    for (int r = 0; r < 16; r++) v[r] = sm[pB + 16*r + (r >> 1)];
    fwht16(v);
#pragma unroll
    for (int r = 0; r < 16; r++) sm[pB + 16*r + (r >> 1)] = v[r];
    __syncthreads();

    // ---- P3: F_C, *g, F_C ----  elem offset 256r -> phys offset 264r
#pragma unroll
    for (int r = 0; r < 16; r++) v[r] = sm[pC + 264*r];
    fwht16(v);
#pragma unroll
    for (int r = 0; r < 16; r++) v[r] *= __ldg(&g_dev[baseC + 256*r]);
    fwht16(v);
#pragma unroll
    for (int r = 0; r < 16; r++) sm[pC + 264*r] = v[r];
    __syncthreads();

    // ---- P4: F_B ----
#pragma unroll
    for (int r = 0; r < 16; r++) v[r] = sm[pB + 16*r + (r >> 1)];
    fwht16(v);
#pragma unroll
    for (int r = 0; r < 16; r++) sm[pB + 16*r + (r >> 1)] = v[r];
    __syncthreads();

    // ---- P5: F_A, *s1, coalesced store ----
#pragma unroll
    for (int r = 0; r < 16; r++) v[r] = sm[pA + r];
    fwht16(v);

    float* orow = out + row * DD;
#pragma unroll
    for (int q = 0; q < 4; q++) {
        float4 s = *reinterpret_cast<const float4*>(s1 + baseA + 4*q);
        float4 o;
        o.x = v[4*q+0] * s.x;
        o.y = v[4*q+1] * s.y;
        o.z = v[4*q+2] * s.z;
        o.w = v[4*q+3] * s.w;
        *reinterpret_cast<float4*>(orow + baseA + 4*q) = o;
    }
}

extern "C" void kernel_launch(void* const* d_in, const int* in_sizes, int n_in,
                              void* d_out, int out_size) {
    const float* x     = (const float*)d_in[0];
    const float* eps   = (const float*)d_in[1];
    const float* s1    = (const float*)d_in[2];
    const float* s2    = (const float*)d_in[3];
    const float* g_mu  = (const float*)d_in[4];
    const float* g_rho = (const float*)d_in[5];
    float* out = (float*)d_out;

    int B = in_sizes[0] / DD;   // 2048

    compute_g_kernel<<<(DD + 255) / 256, 256>>>(eps, g_mu, g_rho);
    whvi_kernel<<<B, 256>>>(x, s1, s2, out);
}